// round 8
// baseline (speedup 1.0000x reference)
#include <cuda_runtime.h>

#define HEADS 4
#define DIM   64
#define BB    8
#define QQ    128
#define VV    128
#define NN    (BB*QQ)   // 1024

typedef unsigned long long ull;

// Scratch (device globals — no allocation allowed). g_VU has one row of pad
// so the recurrence can prefetch one step past the end unconditionally.
__device__ float2 g_QU[HEADS * NN * DIM];                 // [h][n][j] complex
__device__ float2 g_VU[HEADS * BB * VV * DIM + DIM];      // [h][b][v][j] complex (+pad)
__device__ float  g_acc[NN * HEADS * DIM];                // [n][h*64+j] real

__device__ __forceinline__ float sqrt_apx(float s) {
    float r; asm("sqrt.approx.f32 %0,%1;" : "=f"(r) : "f"(s)); return r;
}
__device__ __forceinline__ float rcp_apx(float s) {
    float r; asm("rcp.approx.f32 %0,%1;" : "=f"(r) : "f"(s)); return r;
}
// f32x2 helpers
__device__ __forceinline__ ull pk(float lo, float hi) {
    ull d; asm("mov.b64 %0,{%1,%2};" : "=l"(d) : "f"(lo), "f"(hi)); return d;
}
__device__ __forceinline__ float lo32(ull a) {
    float x; asm("{ .reg .b32 t; mov.b64 {%0,t},%1; }" : "=f"(x) : "l"(a)); return x;
}
__device__ __forceinline__ float hi32(ull a) {
    float x; asm("{ .reg .b32 t; mov.b64 {t,%0},%1; }" : "=f"(x) : "l"(a)); return x;
}
__device__ __forceinline__ ull swp(ull a) {
    ull d; asm("{ .reg .b32 lo,hi; mov.b64 {lo,hi},%1; mov.b64 %0,{hi,lo}; }"
               : "=l"(d) : "l"(a)); return d;
}
__device__ __forceinline__ ull fma2(ull a, ull b, ull c) {
    ull d; asm("fma.rn.f32x2 %0,%1,%2,%3;" : "=l"(d) : "l"(a), "l"(b), "l"(c)); return d;
}
__device__ __forceinline__ ull mul2(ull a, ull b) {
    ull d; asm("mul.rn.f32x2 %0,%1,%2;" : "=l"(d) : "l"(a), "l"(b)); return d;
}
__device__ __forceinline__ ull add2(ull a, ull b) {
    ull d; asm("add.rn.f32x2 %0,%1,%2;" : "=l"(d) : "l"(a), "l"(b)); return d;
}

// modrelu on a packed (re,im) value: sc = max(1 + bp*rcp(|z|+1e-5), 0); z*sc
__device__ __forceinline__ ull modrelu(ull z, float bp) {
    float zr = lo32(z), zi = hi32(z);
    float s  = fmaf(zi, zi, zr * zr);
    float m  = sqrt_apx(s);
    float r  = rcp_apx(m + 1e-5f);
    float sc = fmaxf(fmaf(bp, r, 1.0f), 0.0f);
    return pk(zr * sc, zi * sc);
}

// ---------------------------------------------------------------------------
// Kernel 1 (tiled GEMM): for part p (0:queries->g_QU, 1:values->g_VU), head h,
// 32-row tile:  out[row, j] = sum_k x[row,k] * U[h, p*64+k, j]  (complex)
// ---------------------------------------------------------------------------
__global__ void __launch_bounds__(256) k_compute_u(
    const float* __restrict__ q,      // [1024,64]
    const float* __restrict__ vals,   // [1024,64]
    const float* __restrict__ Ure,    // [4,128,64]
    const float* __restrict__ Uim)
{
    __shared__ float x_s[32 * 64];    // [r][k]
    __shared__ float ur_s[64 * 64];   // [k][j]
    __shared__ float ui_s[64 * 64];

    int t    = threadIdx.x;
    int tile = blockIdx.x & 31;
    int p    = (blockIdx.x >> 5) & 1;
    int h    = blockIdx.x >> 6;

    const float4* src4 = (const float4*)((p == 0 ? q : vals) + tile * 32 * 64);
    float4* xs4 = (float4*)x_s;
    #pragma unroll
    for (int i = 0; i < 2; i++) xs4[t + 256 * i] = __ldg(src4 + t + 256 * i);

    const float4* ur4 = (const float4*)(Ure + h * 8192 + p * 4096);
    const float4* ui4 = (const float4*)(Uim + h * 8192 + p * 4096);
    float4* urs4 = (float4*)ur_s;
    float4* uis4 = (float4*)ui_s;
    #pragma unroll
    for (int i = 0; i < 4; i++) {
        urs4[t + 256 * i] = __ldg(ur4 + t + 256 * i);
        uis4[t + 256 * i] = __ldg(ui4 + t + 256 * i);
    }
    __syncthreads();

    int j0 = t & 31, j1 = j0 + 32, rg = t >> 5;

    float a0r[4], a0i[4], a1r[4], a1i[4];
    #pragma unroll
    for (int i = 0; i < 4; i++) { a0r[i] = a0i[i] = a1r[i] = a1i[i] = 0.f; }

    #pragma unroll 8
    for (int k = 0; k < 64; k++) {
        float u0r = ur_s[k * 64 + j0];
        float u1r = ur_s[k * 64 + j1];
        float u0i = ui_s[k * 64 + j0];
        float u1i = ui_s[k * 64 + j1];
        #pragma unroll
        for (int i = 0; i < 4; i++) {
            float xv = x_s[(rg * 4 + i) * 64 + k];
            a0r[i] = fmaf(xv, u0r, a0r[i]);
            a0i[i] = fmaf(xv, u0i, a0i[i]);
            a1r[i] = fmaf(xv, u1r, a1r[i]);
            a1i[i] = fmaf(xv, u1i, a1i[i]);
        }
    }

    float2* dst = (p == 0 ? g_QU : g_VU) + (size_t)h * NN * DIM + (size_t)tile * 32 * DIM;
    #pragma unroll
    for (int i = 0; i < 4; i++) {
        int row = rg * 4 + i;
        dst[row * DIM + j0] = make_float2(a0r[i], a0i[i]);
        dst[row * DIM + j1] = make_float2(a1r[i], a1i[i]);
    }
}

// ---------------------------------------------------------------------------
// Kernel 2: EUNN+modrelu recurrence. One warp handles TWO states (h, n0) and
// (h, n0+1) — same head, same batch b, so rotation constants AND the VU
// stream are shared. Lane l owns complex elems 2l (A) and 2l+1 (B) of both
// states, packed (re,im) in f32x2 pairs.
// Folded math per state:
//   tA = c1*A - s1*B ; nB = s1*A + c1*B        (packed, real coeffs)
//   zB = P*nB - Q*xd + in ;  zA = G'*tA + F*xu + in   (packed via swap trick)
//   xd = tA of lane l+1, xu = nB of lane l-1
// ---------------------------------------------------------------------------
__global__ void __launch_bounds__(64) k_recur(
    const float* __restrict__ bias,   // [4,64]
    const float* __restrict__ th1,    // [4,32]
    const float* __restrict__ ph1,    // [4,32]
    const float* __restrict__ th2,    // [4,31]
    const float* __restrict__ ph2,    // [4,31]
    const float* __restrict__ om)     // [4,64]
{
    const unsigned FULL = 0xffffffffu;
    int w = (blockIdx.x * blockDim.x + threadIdx.x) >> 5;   // 0..2047
    int l = threadIdx.x & 31;
    int h  = w >> 9;                 // 512 warps per head
    int n0 = (w & 511) << 1;         // even n; states n0, n0+1 share b
    int b  = n0 >> 7;

    // layer-1 constants
    float c1, s1, e1r, e1i;
    sincosf(th1[h * 32 + l], &s1, &c1);
    sincosf(ph1[h * 32 + l], &e1i, &e1r);

    // layer-2 constants (pair l couples elems 2l+1, 2l+2)
    float c2 = 1.f, s2 = 0.f, p2 = 0.f;
    if (l < 31) {
        sincosf(th2[h * 31 + l], &s2, &c2);
        p2 = ph2[h * 31 + l];
    }
    float c2p = 1.f, s2p = 0.f;
    if (l > 0) sincosf(th2[h * 31 + l - 1], &s2p, &c2p);

    float omA = om[h * 64 + 2 * l];
    float omB = om[h * 64 + 2 * l + 1];

    // e1 of lane l+1 (lane 31: unused, s2=0 kills it)
    float e1nr = __shfl_down_sync(FULL, e1r, 1);
    float e1ni = __shfl_down_sync(FULL, e1i, 1);

    // E = e^{i(omB + phi2_l)}; P = E*c2; Q = E*s2*e1_next
    float Er, Ei;
    sincosf(omB + p2, &Ei, &Er);
    float Pr = c2 * Er, Pi = c2 * Ei;
    float Qr = s2 * (Er * e1nr - Ei * e1ni);
    float Qi = s2 * (Er * e1ni + Ei * e1nr);
    // G' = e^{i omA}*c2p*e1 ; F = e^{i omA}*s2p
    float cA_, sA_;
    sincosf(omA, &sA_, &cA_);
    float Gr = c2p * (cA_ * e1r - sA_ * e1i);
    float Gi = c2p * (cA_ * e1i + sA_ * e1r);
    float Fr = s2p * cA_, Fi = s2p * sA_;

    float bAp = bias[h * 64 + 2 * l]     - 1e-5f;
    float bBp = bias[h * 64 + 2 * l + 1] - 1e-5f;

    // packed constants (shared by both states)
    ull c1p = pk(c1, c1), s1p = pk(s1, s1), ns1p = pk(-s1, -s1);
    ull PrP = pk(Pr, Pr),  PiM = pk(-Pi, Pi);
    ull QrN = pk(-Qr, -Qr), QiM = pk(Qi, -Qi);
    ull GrP = pk(Gr, Gr),  GiM = pk(-Gi, Gi);
    ull FrP = pk(Fr, Fr),  FiM = pk(-Fi, Fi);

    // per-state constant inputs (QU) and shared VU stream
    float4 qu0 = __ldg((const float4*)&g_QU[(h * NN + n0) * DIM + 2 * l]);
    float4 qu1 = __ldg((const float4*)&g_QU[(h * NN + n0 + 1) * DIM + 2 * l]);
    ull quA0 = pk(qu0.x, qu0.y), quB0 = pk(qu0.z, qu0.w);
    ull quA1 = pk(qu1.x, qu1.y), quB1 = pk(qu1.z, qu1.w);
    const float4* vup = (const float4*)&g_VU[((h * BB + b) * VV) * DIM + 2 * l];

    ull A0 = 0ull, B0 = 0ull, A1 = 0ull, B1 = 0ull;

    float4 vu = __ldg(vup); vup += DIM / 2;   // prefetch step 0

    #pragma unroll 2
    for (int v = 0; v < VV; v++) {
        float4 vun = __ldg(vup); vup += DIM / 2;   // prefetch next (pad covers v=127)

        ull vuA = pk(vu.x, vu.y), vuB = pk(vu.z, vu.w);
        ull inA0 = add2(quA0, vuA), inB0 = add2(quB0, vuB);
        ull inA1 = add2(quA1, vuA), inB1 = add2(quB1, vuB);

        // layer 1 (packed, real coefficients) — both states
        ull tA0 = fma2(c1p, A0, mul2(ns1p, B0));
        ull nB0 = fma2(s1p, A0, mul2(c1p, B0));
        ull tA1 = fma2(c1p, A1, mul2(ns1p, B1));
        ull nB1 = fma2(s1p, A1, mul2(c1p, B1));

        // cross-lane exchanges (independent between states)
        ull xu0 = __shfl_up_sync(FULL, nB0, 1);
        ull xd0 = __shfl_down_sync(FULL, tA0, 1);
        ull xu1 = __shfl_up_sync(FULL, nB1, 1);
        ull xd1 = __shfl_down_sync(FULL, tA1, 1);

        // zB = P*nB - Q*xd + in  (packed complex via swap trick)
        ull zB0 = fma2(PrP, nB0, fma2(PiM, swp(nB0),
                  fma2(QrN, xd0, fma2(QiM, swp(xd0), inB0))));
        ull zA0 = fma2(GrP, tA0, fma2(GiM, swp(tA0),
                  fma2(FrP, xu0, fma2(FiM, swp(xu0), inA0))));
        ull zB1 = fma2(PrP, nB1, fma2(PiM, swp(nB1),
                  fma2(QrN, xd1, fma2(QiM, swp(xd1), inB1))));
        ull zA1 = fma2(GrP, tA1, fma2(GiM, swp(tA1),
                  fma2(FrP, xu1, fma2(FiM, swp(xu1), inA1))));

        // modrelu (4 independent chains)
        A0 = modrelu(zA0, bAp);
        B0 = modrelu(zB0, bBp);
        A1 = modrelu(zA1, bAp);
        B1 = modrelu(zB1, bBp);

        vu = vun;
    }

    float2* acc0 = (float2*)&g_acc[n0 * (HEADS * DIM) + h * DIM + 2 * l];
    *acc0 = make_float2(lo32(A0), lo32(B0));
    float2* acc1 = (float2*)&g_acc[(n0 + 1) * (HEADS * DIM) + h * DIM + 2 * l];
    *acc1 = make_float2(lo32(A1), lo32(B1));
}

// ---------------------------------------------------------------------------
// Kernel 3: y = acc @ W + b   ([1024,256] @ [256,64])
// ---------------------------------------------------------------------------
#define AST 264
__global__ void __launch_bounds__(256) k_proj(
    const float* __restrict__ W,    // [256,64]
    const float* __restrict__ bd,   // [64]
    float* __restrict__ out)        // [1024,64]
{
    __shared__ float a_s[16 * AST];
    int t = threadIdx.x;
    int row0 = blockIdx.x * 16;

    const float4* g4 = (const float4*)(g_acc + row0 * 256);
    #pragma unroll
    for (int i = 0; i < 4; i++) {
        int g = t + 256 * i;
        int r = g >> 6, c4 = g & 63;
        *(float4*)&a_s[r * AST + c4 * 4] = __ldg(g4 + g);
    }
    __syncthreads();

    int tx = t & 15, ty = t >> 4;
    float4 s = __ldg((const float4*)(bd + 4 * tx));
    const float* arow = a_s + ty * AST;

    #pragma unroll 4
    for (int k = 0; k < 256; k++) {
        float a = arow[k];
        float4 wv = __ldg((const float4*)(W + k * 64 + 4 * tx));
        s.x = fmaf(a, wv.x, s.x);
        s.y = fmaf(a, wv.y, s.y);
        s.z = fmaf(a, wv.z, s.z);
        s.w = fmaf(a, wv.w, s.w);
    }
    *(float4*)(out + (row0 + ty) * 64 + 4 * tx) = s;
}

// ---------------------------------------------------------------------------
extern "C" void kernel_launch(void* const* d_in, const int* in_sizes, int n_in,
                              void* d_out, int out_size)
{
    const float* queries = (const float*)d_in[0];
    const float* values  = (const float*)d_in[1];
    const float* U_re    = (const float*)d_in[2];
    const float* U_im    = (const float*)d_in[3];
    const float* bias    = (const float*)d_in[4];
    const float* theta1  = (const float*)d_in[5];
    const float* phi1    = (const float*)d_in[6];
    const float* theta2  = (const float*)d_in[7];
    const float* phi2    = (const float*)d_in[8];
    const float* omega   = (const float*)d_in[9];
    const float* W_dense = (const float*)d_in[10];
    const float* b_dense = (const float*)d_in[11];
    float* out = (float*)d_out;

    k_compute_u<<<256, 256>>>(queries, values, U_re, U_im);
    k_recur<<<1024, 64>>>(bias, theta1, phi1, theta2, phi2, omega);
    k_proj<<<64, 256>>>(W_dense, b_dense, out);
}

// round 9
// speedup vs baseline: 1.0522x; 1.0522x over previous
#include <cuda_runtime.h>

#define HEADS 4
#define DIM   64
#define BB    8
#define QQ    128
#define VV    128
#define NN    (BB*QQ)   // 1024

typedef unsigned long long ull;

// Scratch (device globals — no allocation allowed). g_VU has one row of pad
// so the recurrence can prefetch one step past the end unconditionally.
__device__ float2 g_QU[HEADS * NN * DIM];                 // [h][n][j] complex
__device__ float2 g_VU[HEADS * BB * VV * DIM + DIM];      // [h][b][v][j] complex (+pad)
__device__ float  g_acc[NN * HEADS * DIM];                // [n][h*64+j] real

__device__ __forceinline__ float sqrt_apx(float s) {
    float r; asm("sqrt.approx.f32 %0,%1;" : "=f"(r) : "f"(s)); return r;
}
__device__ __forceinline__ float rcp_apx(float s) {
    float r; asm("rcp.approx.f32 %0,%1;" : "=f"(r) : "f"(s)); return r;
}
// f32x2 helpers (real-coefficient packing only; no swaps)
__device__ __forceinline__ ull pk(float lo, float hi) {
    ull d; asm("mov.b64 %0,{%1,%2};" : "=l"(d) : "f"(lo), "f"(hi)); return d;
}
__device__ __forceinline__ float lo32(ull a) {
    float x; asm("{ .reg .b32 t; mov.b64 {%0,t},%1; }" : "=f"(x) : "l"(a)); return x;
}
__device__ __forceinline__ float hi32(ull a) {
    float x; asm("{ .reg .b32 t; mov.b64 {t,%0},%1; }" : "=f"(x) : "l"(a)); return x;
}
__device__ __forceinline__ ull fma2(ull a, ull b, ull c) {
    ull d; asm("fma.rn.f32x2 %0,%1,%2,%3;" : "=l"(d) : "l"(a), "l"(b), "l"(c)); return d;
}
__device__ __forceinline__ ull mul2(ull a, ull b) {
    ull d; asm("mul.rn.f32x2 %0,%1,%2;" : "=l"(d) : "l"(a), "l"(b)); return d;
}
__device__ __forceinline__ ull add2(ull a, ull b) {
    ull d; asm("add.rn.f32x2 %0,%1,%2;" : "=l"(d) : "l"(a), "l"(b)); return d;
}

// ---------------------------------------------------------------------------
// Kernel 1 (tiled GEMM): for part p (0:queries->g_QU, 1:values->g_VU), head h,
// 32-row tile:  out[row, j] = sum_k x[row,k] * U[h, p*64+k, j]  (complex)
// ---------------------------------------------------------------------------
__global__ void __launch_bounds__(256) k_compute_u(
    const float* __restrict__ q,      // [1024,64]
    const float* __restrict__ vals,   // [1024,64]
    const float* __restrict__ Ure,    // [4,128,64]
    const float* __restrict__ Uim)
{
    __shared__ float x_s[32 * 64];    // [r][k]
    __shared__ float ur_s[64 * 64];   // [k][j]
    __shared__ float ui_s[64 * 64];

    int t    = threadIdx.x;
    int tile = blockIdx.x & 31;
    int p    = (blockIdx.x >> 5) & 1;
    int h    = blockIdx.x >> 6;

    const float4* src4 = (const float4*)((p == 0 ? q : vals) + tile * 32 * 64);
    float4* xs4 = (float4*)x_s;
    #pragma unroll
    for (int i = 0; i < 2; i++) xs4[t + 256 * i] = __ldg(src4 + t + 256 * i);

    const float4* ur4 = (const float4*)(Ure + h * 8192 + p * 4096);
    const float4* ui4 = (const float4*)(Uim + h * 8192 + p * 4096);
    float4* urs4 = (float4*)ur_s;
    float4* uis4 = (float4*)ui_s;
    #pragma unroll
    for (int i = 0; i < 4; i++) {
        urs4[t + 256 * i] = __ldg(ur4 + t + 256 * i);
        uis4[t + 256 * i] = __ldg(ui4 + t + 256 * i);
    }
    __syncthreads();

    int j0 = t & 31, j1 = j0 + 32, rg = t >> 5;

    float a0r[4], a0i[4], a1r[4], a1i[4];
    #pragma unroll
    for (int i = 0; i < 4; i++) { a0r[i] = a0i[i] = a1r[i] = a1i[i] = 0.f; }

    #pragma unroll 8
    for (int k = 0; k < 64; k++) {
        float u0r = ur_s[k * 64 + j0];
        float u1r = ur_s[k * 64 + j1];
        float u0i = ui_s[k * 64 + j0];
        float u1i = ui_s[k * 64 + j1];
        #pragma unroll
        for (int i = 0; i < 4; i++) {
            float xv = x_s[(rg * 4 + i) * 64 + k];
            a0r[i] = fmaf(xv, u0r, a0r[i]);
            a0i[i] = fmaf(xv, u0i, a0i[i]);
            a1r[i] = fmaf(xv, u1r, a1r[i]);
            a1i[i] = fmaf(xv, u1i, a1i[i]);
        }
    }

    float2* dst = (p == 0 ? g_QU : g_VU) + (size_t)h * NN * DIM + (size_t)tile * 32 * DIM;
    #pragma unroll
    for (int i = 0; i < 4; i++) {
        int row = rg * 4 + i;
        dst[row * DIM + j0] = make_float2(a0r[i], a0i[i]);
        dst[row * DIM + j1] = make_float2(a1r[i], a1i[i]);
    }
}

// ---------------------------------------------------------------------------
// Kernel 2: EUNN+modrelu recurrence. One warp handles TWO states (h,n0) and
// (h,n0+1) — same head, same batch, shared constants and VU stream. Per-state
// math is EXACTLY the R7 (68.1us) body: layer-1 + input adds packed f32x2
// (real coefficients, no swaps), z-section and modrelu scalar.
//   tA = c1*A - s1*B ; nB = s1*A + c1*B
//   zB = P*nB - Q*xd + in,  P = E*c2, Q = E*s2*e1_{l+1}, E = e^{i(wB+phi2_l)}
//   zA = G'*tA + F*xu + in, G' = e^{i wA}*c2p*e1, F = e^{i wA}*s2p
//   xd = tA of lane l+1, xu = nB of lane l-1
//   modrelu: sc = max(1 + (b-1e-5)*rcp(|z|+1e-5), 0);  h = z*sc
// ---------------------------------------------------------------------------
__global__ void __launch_bounds__(128, 4) k_recur(
    const float* __restrict__ bias,   // [4,64]
    const float* __restrict__ th1,    // [4,32]
    const float* __restrict__ ph1,    // [4,32]
    const float* __restrict__ th2,    // [4,31]
    const float* __restrict__ ph2,    // [4,31]
    const float* __restrict__ om)     // [4,64]
{
    const unsigned FULL = 0xffffffffu;
    int w = (blockIdx.x * blockDim.x + threadIdx.x) >> 5;   // 0..2047
    int l = threadIdx.x & 31;
    int h  = w >> 9;                 // 512 warps per head
    int n0 = (w & 511) << 1;         // states n0, n0+1 share b
    int b  = n0 >> 7;

    // layer-1 constants
    float c1, s1, e1r, e1i;
    sincosf(th1[h * 32 + l], &s1, &c1);
    sincosf(ph1[h * 32 + l], &e1i, &e1r);

    // layer-2 constants (pair l couples elems 2l+1, 2l+2)
    float c2 = 1.f, s2 = 0.f, p2 = 0.f;
    if (l < 31) {
        sincosf(th2[h * 31 + l], &s2, &c2);
        p2 = ph2[h * 31 + l];
    }
    float c2p = 1.f, s2p = 0.f;
    if (l > 0) sincosf(th2[h * 31 + l - 1], &s2p, &c2p);

    float omA = om[h * 64 + 2 * l];
    float omB = om[h * 64 + 2 * l + 1];

    // e1 of lane l+1 (lane 31: unused, s2=0 kills it)
    float e1nr = __shfl_down_sync(FULL, e1r, 1);
    float e1ni = __shfl_down_sync(FULL, e1i, 1);

    // E = e^{i(omB + phi2_l)}; P = E*c2; Q = E*s2*e1_next
    float Er, Ei;
    sincosf(omB + p2, &Ei, &Er);
    float Pr = c2 * Er, Pi = c2 * Ei;
    float Qr = s2 * (Er * e1nr - Ei * e1ni);
    float Qi = s2 * (Er * e1ni + Ei * e1nr);
    // G' = e^{i omA}*c2p*e1 ; F = e^{i omA}*s2p
    float cA_, sA_;
    sincosf(omA, &sA_, &cA_);
    float Gr = c2p * (cA_ * e1r - sA_ * e1i);
    float Gi = c2p * (cA_ * e1i + sA_ * e1r);
    float Fr = s2p * cA_, Fi = s2p * sA_;

    float bAp = bias[h * 64 + 2 * l]     - 1e-5f;
    float bBp = bias[h * 64 + 2 * l + 1] - 1e-5f;

    // packed real-coefficient constants for layer 1
    ull c1p  = pk(c1, c1);
    ull s1p  = pk(s1, s1);
    ull ns1p = pk(-s1, -s1);

    // per-state constant inputs (QU) and shared VU stream
    float4 qu0 = __ldg((const float4*)&g_QU[(h * NN + n0) * DIM + 2 * l]);
    float4 qu1 = __ldg((const float4*)&g_QU[(h * NN + n0 + 1) * DIM + 2 * l]);
    ull quA0 = pk(qu0.x, qu0.y), quB0 = pk(qu0.z, qu0.w);
    ull quA1 = pk(qu1.x, qu1.y), quB1 = pk(qu1.z, qu1.w);
    const float4* vup = (const float4*)&g_VU[((h * BB + b) * VV) * DIM + 2 * l];

    ull A0 = 0ull, B0 = 0ull, A1 = 0ull, B1 = 0ull;

    float4 vu = __ldg(vup); vup += DIM / 2;   // prefetch step 0

    #pragma unroll 2
    for (int v = 0; v < VV; v++) {
        float4 vun = __ldg(vup); vup += DIM / 2;   // prefetch next (pad covers v=127)

        ull vuA = pk(vu.x, vu.y), vuB = pk(vu.z, vu.w);

        // ---- state 0 ----
        {
            ull inA2 = add2(quA0, vuA);
            ull inB2 = add2(quB0, vuB);

            ull tA2 = fma2(c1p, A0, mul2(ns1p, B0));
            ull nB2 = fma2(s1p, A0, mul2(c1p, B0));

            ull xu2 = __shfl_up_sync(FULL, nB2, 1);
            ull xd2 = __shfl_down_sync(FULL, tA2, 1);

            float nBr = lo32(nB2), nBi = hi32(nB2);
            float tAr = lo32(tA2), tAi = hi32(tA2);
            float xur = lo32(xu2), xui = hi32(xu2);
            float xdr = lo32(xd2), xdi = hi32(xd2);
            float inAr = lo32(inA2), inAi = hi32(inA2);
            float inBr = lo32(inB2), inBi = hi32(inB2);

            float zBr = fmaf(Pr, nBr, fmaf(-Pi, nBi, fmaf(-Qr, xdr, fmaf( Qi, xdi, inBr))));
            float zBi = fmaf(Pr, nBi, fmaf( Pi, nBr, fmaf(-Qr, xdi, fmaf(-Qi, xdr, inBi))));
            float zAr = fmaf(Gr, tAr, fmaf(-Gi, tAi, fmaf(Fr, xur, fmaf(-Fi, xui, inAr))));
            float zAi = fmaf(Gr, tAi, fmaf( Gi, tAr, fmaf(Fr, xui, fmaf( Fi, xur, inAi))));

            float sA = fmaf(zAi, zAi, zAr * zAr);
            float mA = sqrt_apx(sA);
            float rA = rcp_apx(mA + 1e-5f);
            float scA = fmaxf(fmaf(bAp, rA, 1.0f), 0.0f);
            A0 = pk(zAr * scA, zAi * scA);

            float sB = fmaf(zBi, zBi, zBr * zBr);
            float mB = sqrt_apx(sB);
            float rB = rcp_apx(mB + 1e-5f);
            float scB = fmaxf(fmaf(bBp, rB, 1.0f), 0.0f);
            B0 = pk(zBr * scB, zBi * scB);
        }

        // ---- state 1 ----
        {
            ull inA2 = add2(quA1, vuA);
            ull inB2 = add2(quB1, vuB);

            ull tA2 = fma2(c1p, A1, mul2(ns1p, B1));
            ull nB2 = fma2(s1p, A1, mul2(c1p, B1));

            ull xu2 = __shfl_up_sync(FULL, nB2, 1);
            ull xd2 = __shfl_down_sync(FULL, tA2, 1);

            float nBr = lo32(nB2), nBi = hi32(nB2);
            float tAr = lo32(tA2), tAi = hi32(tA2);
            float xur = lo32(xu2), xui = hi32(xu2);
            float xdr = lo32(xd2), xdi = hi32(xd2);
            float inAr = lo32(inA2), inAi = hi32(inA2);
            float inBr = lo32(inB2), inBi = hi32(inB2);

            float zBr = fmaf(Pr, nBr, fmaf(-Pi, nBi, fmaf(-Qr, xdr, fmaf( Qi, xdi, inBr))));
            float zBi = fmaf(Pr, nBi, fmaf( Pi, nBr, fmaf(-Qr, xdi, fmaf(-Qi, xdr, inBi))));
            float zAr = fmaf(Gr, tAr, fmaf(-Gi, tAi, fmaf(Fr, xur, fmaf(-Fi, xui, inAr))));
            float zAi = fmaf(Gr, tAi, fmaf( Gi, tAr, fmaf(Fr, xui, fmaf( Fi, xur, inAi))));

            float sA = fmaf(zAi, zAi, zAr * zAr);
            float mA = sqrt_apx(sA);
            float rA = rcp_apx(mA + 1e-5f);
            float scA = fmaxf(fmaf(bAp, rA, 1.0f), 0.0f);
            A1 = pk(zAr * scA, zAi * scA);

            float sB = fmaf(zBi, zBi, zBr * zBr);
            float mB = sqrt_apx(sB);
            float rB = rcp_apx(mB + 1e-5f);
            float scB = fmaxf(fmaf(bBp, rB, 1.0f), 0.0f);
            B1 = pk(zBr * scB, zBi * scB);
        }

        vu = vun;
    }

    float2* acc0 = (float2*)&g_acc[n0 * (HEADS * DIM) + h * DIM + 2 * l];
    *acc0 = make_float2(lo32(A0), lo32(B0));
    float2* acc1 = (float2*)&g_acc[(n0 + 1) * (HEADS * DIM) + h * DIM + 2 * l];
    *acc1 = make_float2(lo32(A1), lo32(B1));
}

// ---------------------------------------------------------------------------
// Kernel 3: y = acc @ W + b   ([1024,256] @ [256,64])
// ---------------------------------------------------------------------------
#define AST 264
__global__ void __launch_bounds__(256) k_proj(
    const float* __restrict__ W,    // [256,64]
    const float* __restrict__ bd,   // [64]
    float* __restrict__ out)        // [1024,64]
{
    __shared__ float a_s[16 * AST];
    int t = threadIdx.x;
    int row0 = blockIdx.x * 16;

    const float4* g4 = (const float4*)(g_acc + row0 * 256);
    #pragma unroll
    for (int i = 0; i < 4; i++) {
        int g = t + 256 * i;
        int r = g >> 6, c4 = g & 63;
        *(float4*)&a_s[r * AST + c4 * 4] = __ldg(g4 + g);
    }
    __syncthreads();

    int tx = t & 15, ty = t >> 4;
    float4 s = __ldg((const float4*)(bd + 4 * tx));
    const float* arow = a_s + ty * AST;

    #pragma unroll 4
    for (int k = 0; k < 256; k++) {
        float a = arow[k];
        float4 wv = __ldg((const float4*)(W + k * 64 + 4 * tx));
        s.x = fmaf(a, wv.x, s.x);
        s.y = fmaf(a, wv.y, s.y);
        s.z = fmaf(a, wv.z, s.z);
        s.w = fmaf(a, wv.w, s.w);
    }
    *(float4*)(out + (row0 + ty) * 64 + 4 * tx) = s;
}

// ---------------------------------------------------------------------------
extern "C" void kernel_launch(void* const* d_in, const int* in_sizes, int n_in,
                              void* d_out, int out_size)
{
    const float* queries = (const float*)d_in[0];
    const float* values  = (const float*)d_in[1];
    const float* U_re    = (const float*)d_in[2];
    const float* U_im    = (const float*)d_in[3];
    const float* bias    = (const float*)d_in[4];
    const float* theta1  = (const float*)d_in[5];
    const float* phi1    = (const float*)d_in[6];
    const float* theta2  = (const float*)d_in[7];
    const float* phi2    = (const float*)d_in[8];
    const float* omega   = (const float*)d_in[9];
    const float* W_dense = (const float*)d_in[10];
    const float* b_dense = (const float*)d_in[11];
    float* out = (float*)d_out;

    k_compute_u<<<256, 256>>>(queries, values, U_re, U_im);
    k_recur<<<512, 128>>>(bias, theta1, phi1, theta2, phi2, omega);
    k_proj<<<64, 256>>>(W_dense, b_dense, out);
}

// round 10
// speedup vs baseline: 1.6859x; 1.6023x over previous
#include <cuda_runtime.h>

#define HEADS 4
#define DIM   64
#define BB    8
#define QQ    128
#define VV    128
#define NN    (BB*QQ)   // 1024

typedef unsigned long long ull;

// Scratch (device globals — no allocation allowed). g_VU has one row of pad
// so the recurrence can prefetch one step past the end unconditionally.
__device__ float2 g_QU[HEADS * NN * DIM];                 // [h][n][j] complex
__device__ float2 g_VU[HEADS * BB * VV * DIM + DIM];      // [h][b][v][j] complex (+pad)
__device__ float  g_acc[NN * HEADS * DIM];                // [n][h*64+j] real

__device__ __forceinline__ float sqrt_apx(float s) {
    float r; asm("sqrt.approx.f32 %0,%1;" : "=f"(r) : "f"(s)); return r;
}
__device__ __forceinline__ float rcp_apx(float s) {
    float r; asm("rcp.approx.f32 %0,%1;" : "=f"(r) : "f"(s)); return r;
}
// f32x2 helpers (real-coefficient packing only; no swaps needed)
__device__ __forceinline__ ull pk(float lo, float hi) {
    ull d; asm("mov.b64 %0,{%1,%2};" : "=l"(d) : "f"(lo), "f"(hi)); return d;
}
__device__ __forceinline__ float lo32(ull a) {
    float x; asm("{ .reg .b32 t; mov.b64 {%0,t},%1; }" : "=f"(x) : "l"(a)); return x;
}
__device__ __forceinline__ float hi32(ull a) {
    float x; asm("{ .reg .b32 t; mov.b64 {t,%0},%1; }" : "=f"(x) : "l"(a)); return x;
}
__device__ __forceinline__ ull fma2(ull a, ull b, ull c) {
    ull d; asm("fma.rn.f32x2 %0,%1,%2,%3;" : "=l"(d) : "l"(a), "l"(b), "l"(c)); return d;
}
__device__ __forceinline__ ull mul2(ull a, ull b) {
    ull d; asm("mul.rn.f32x2 %0,%1,%2;" : "=l"(d) : "l"(a), "l"(b)); return d;
}
__device__ __forceinline__ ull add2(ull a, ull b) {
    ull d; asm("add.rn.f32x2 %0,%1,%2;" : "=l"(d) : "l"(a), "l"(b)); return d;
}

// ---------------------------------------------------------------------------
// Kernel 1 (tiled GEMM): for part p (0:queries->g_QU, 1:values->g_VU), head h,
// 32-row tile:  out[row, j] = sum_k x[row,k] * U[h, p*64+k, j]  (complex)
// ---------------------------------------------------------------------------
__global__ void __launch_bounds__(256) k_compute_u(
    const float* __restrict__ q,      // [1024,64]
    const float* __restrict__ vals,   // [1024,64]
    const float* __restrict__ Ure,    // [4,128,64]
    const float* __restrict__ Uim)
{
    __shared__ float x_s[32 * 64];    // [r][k]
    __shared__ float ur_s[64 * 64];   // [k][j]
    __shared__ float ui_s[64 * 64];

    int t    = threadIdx.x;
    int tile = blockIdx.x & 31;
    int p    = (blockIdx.x >> 5) & 1;
    int h    = blockIdx.x >> 6;

    const float4* src4 = (const float4*)((p == 0 ? q : vals) + tile * 32 * 64);
    float4* xs4 = (float4*)x_s;
    #pragma unroll
    for (int i = 0; i < 2; i++) xs4[t + 256 * i] = __ldg(src4 + t + 256 * i);

    const float4* ur4 = (const float4*)(Ure + h * 8192 + p * 4096);
    const float4* ui4 = (const float4*)(Uim + h * 8192 + p * 4096);
    float4* urs4 = (float4*)ur_s;
    float4* uis4 = (float4*)ui_s;
    #pragma unroll
    for (int i = 0; i < 4; i++) {
        urs4[t + 256 * i] = __ldg(ur4 + t + 256 * i);
        uis4[t + 256 * i] = __ldg(ui4 + t + 256 * i);
    }
    __syncthreads();

    int j0 = t & 31, j1 = j0 + 32, rg = t >> 5;

    float a0r[4], a0i[4], a1r[4], a1i[4];
    #pragma unroll
    for (int i = 0; i < 4; i++) { a0r[i] = a0i[i] = a1r[i] = a1i[i] = 0.f; }

    #pragma unroll 8
    for (int k = 0; k < 64; k++) {
        float u0r = ur_s[k * 64 + j0];
        float u1r = ur_s[k * 64 + j1];
        float u0i = ui_s[k * 64 + j0];
        float u1i = ui_s[k * 64 + j1];
        #pragma unroll
        for (int i = 0; i < 4; i++) {
            float xv = x_s[(rg * 4 + i) * 64 + k];
            a0r[i] = fmaf(xv, u0r, a0r[i]);
            a0i[i] = fmaf(xv, u0i, a0i[i]);
            a1r[i] = fmaf(xv, u1r, a1r[i]);
            a1i[i] = fmaf(xv, u1i, a1i[i]);
        }
    }

    float2* dst = (p == 0 ? g_QU : g_VU) + (size_t)h * NN * DIM + (size_t)tile * 32 * DIM;
    #pragma unroll
    for (int i = 0; i < 4; i++) {
        int row = rg * 4 + i;
        dst[row * DIM + j0] = make_float2(a0r[i], a0i[i]);
        dst[row * DIM + j1] = make_float2(a1r[i], a1i[i]);
    }
}

// ---------------------------------------------------------------------------
// Kernel 2: EUNN+modrelu recurrence — EXACT R7 body (best measured), one warp
// per (h, n). Lane l owns complex elems 2l (A) and 2l+1 (B), state packed
// (re,im) in f32x2 pairs. Only the launch geometry changed (128-thr blocks
// for fine-grained SM load balance).
// Folded form (nA never materialized):
//   tA = c1*A - s1*B ; nB = s1*A + c1*B         (packed f32x2, real coeffs)
//   zB = P*nB - Q*xd + in,   P = E*c2,  Q = E*s2*e1_{l+1},  E = e^{i(wB+phi2_l)}
//   zA = G'*tA + F*xu + in,  G' = e^{i wA}*c2p*e1,  F = e^{i wA}*s2p
//   xd = tA of lane l+1, xu = nB of lane l-1
//   modrelu: sc = max(1 + (b-1e-5)*rcp(|z|+1e-5), 0);  h = z*sc
// ---------------------------------------------------------------------------
__global__ void __launch_bounds__(128) k_recur(
    const float* __restrict__ bias,   // [4,64]
    const float* __restrict__ th1,    // [4,32]
    const float* __restrict__ ph1,    // [4,32]
    const float* __restrict__ th2,    // [4,31]
    const float* __restrict__ ph2,    // [4,31]
    const float* __restrict__ om)     // [4,64]
{
    const unsigned FULL = 0xffffffffu;
    int w = (blockIdx.x * blockDim.x + threadIdx.x) >> 5;   // 0..4095
    int l = threadIdx.x & 31;
    int h = w >> 10;
    int n = w & (NN - 1);
    int b = n >> 7;

    // layer-1 constants
    float c1, s1, e1r, e1i;
    sincosf(th1[h * 32 + l], &s1, &c1);
    sincosf(ph1[h * 32 + l], &e1i, &e1r);

    // layer-2 constants (pair l couples elems 2l+1, 2l+2)
    float c2 = 1.f, s2 = 0.f, p2 = 0.f;
    if (l < 31) {
        sincosf(th2[h * 31 + l], &s2, &c2);
        p2 = ph2[h * 31 + l];
    }
    float c2p = 1.f, s2p = 0.f;
    if (l > 0) sincosf(th2[h * 31 + l - 1], &s2p, &c2p);

    float omA = om[h * 64 + 2 * l];
    float omB = om[h * 64 + 2 * l + 1];

    // e1 of lane l+1 (lane 31: unused, s2=0 kills it)
    float e1nr = __shfl_down_sync(FULL, e1r, 1);
    float e1ni = __shfl_down_sync(FULL, e1i, 1);

    // E = e^{i(omB + phi2_l)}; P = E*c2; Q = E*s2*e1_next
    float Er, Ei;
    sincosf(omB + p2, &Ei, &Er);
    float Pr = c2 * Er, Pi = c2 * Ei;
    float Qr = s2 * (Er * e1nr - Ei * e1ni);
    float Qi = s2 * (Er * e1ni + Ei * e1nr);
    // G' = e^{i omA}*c2p*e1 ; F = e^{i omA}*s2p
    float cA_, sA_;
    sincosf(omA, &sA_, &cA_);
    float Gr = c2p * (cA_ * e1r - sA_ * e1i);
    float Gi = c2p * (cA_ * e1i + sA_ * e1r);
    float Fr = s2p * cA_, Fi = s2p * sA_;

    float bAp = bias[h * 64 + 2 * l]     - 1e-5f;
    float bBp = bias[h * 64 + 2 * l + 1] - 1e-5f;

    // packed real-coefficient constants for layer 1
    ull c1p  = pk(c1, c1);
    ull s1p  = pk(s1, s1);
    ull ns1p = pk(-s1, -s1);

    // per-warp constant input (QU) and per-step VU stream
    float4 qu = __ldg((const float4*)&g_QU[(h * NN + n) * DIM + 2 * l]);
    ull quA2 = pk(qu.x, qu.y);
    ull quB2 = pk(qu.z, qu.w);
    const float4* vup = (const float4*)&g_VU[((h * BB + b) * VV) * DIM + 2 * l];

    ull A2 = 0ull, B2 = 0ull;   // (re, im) packed state

    float4 vu = __ldg(vup); vup += DIM / 2;   // prefetch step 0

    #pragma unroll 4
    for (int v = 0; v < VV; v++) {
        float4 vun = __ldg(vup); vup += DIM / 2;   // prefetch next (pad covers v=127)

        // input term (packed adds)
        ull inA2 = add2(quA2, pk(vu.x, vu.y));
        ull inB2 = add2(quB2, pk(vu.z, vu.w));

        // layer 1 (packed, real coefficients)
        ull tA2 = fma2(c1p, A2, mul2(ns1p, B2));   // c1*A - s1*B  (re,im)
        ull nB2 = fma2(s1p, A2, mul2(c1p, B2));    // s1*A + c1*B  (re,im)

        // cross-lane exchange (64-bit shfl = 2 SHFL each)
        ull xu2 = __shfl_up_sync(FULL, nB2, 1);    // nB of lane l-1
        ull xd2 = __shfl_down_sync(FULL, tA2, 1);  // tA of lane l+1

        float nBr = lo32(nB2), nBi = hi32(nB2);
        float tAr = lo32(tA2), tAi = hi32(tA2);
        float xur = lo32(xu2), xui = hi32(xu2);
        float xdr = lo32(xd2), xdi = hi32(xd2);
        float inAr = lo32(inA2), inAi = hi32(inA2);
        float inBr = lo32(inB2), inBi = hi32(inB2);

        // B path: zB = P*nB - Q*xd + in   (complex, folded)
        float zBr = fmaf(Pr, nBr, fmaf(-Pi, nBi, fmaf(-Qr, xdr, fmaf( Qi, xdi, inBr))));
        float zBi = fmaf(Pr, nBi, fmaf( Pi, nBr, fmaf(-Qr, xdi, fmaf(-Qi, xdr, inBi))));

        // A path: zA = G'*tA + F*xu + in  (complex, folded)
        float zAr = fmaf(Gr, tAr, fmaf(-Gi, tAi, fmaf(Fr, xur, fmaf(-Fi, xui, inAr))));
        float zAi = fmaf(Gr, tAi, fmaf( Gi, tAr, fmaf(Fr, xui, fmaf( Fi, xur, inAi))));

        // modrelu A
        float sA = fmaf(zAi, zAi, zAr * zAr);
        float mA = sqrt_apx(sA);
        float rA = rcp_apx(mA + 1e-5f);
        float scA = fmaxf(fmaf(bAp, rA, 1.0f), 0.0f);
        A2 = pk(zAr * scA, zAi * scA);

        // modrelu B
        float sB = fmaf(zBi, zBi, zBr * zBr);
        float mB = sqrt_apx(sB);
        float rB = rcp_apx(mB + 1e-5f);
        float scB = fmaxf(fmaf(bBp, rB, 1.0f), 0.0f);
        B2 = pk(zBr * scB, zBi * scB);

        vu = vun;
    }

    float2* accp = (float2*)&g_acc[n * (HEADS * DIM) + h * DIM + 2 * l];
    *accp = make_float2(lo32(A2), lo32(B2));
}

// ---------------------------------------------------------------------------
// Kernel 3: y = acc @ W + b   ([1024,256] @ [256,64])
// ---------------------------------------------------------------------------
#define AST 264
__global__ void __launch_bounds__(256) k_proj(
    const float* __restrict__ W,    // [256,64]
    const float* __restrict__ bd,   // [64]
    float* __restrict__ out)        // [1024,64]
{
    __shared__ float a_s[16 * AST];
    int t = threadIdx.x;
    int row0 = blockIdx.x * 16;

    const float4* g4 = (const float4*)(g_acc + row0 * 256);
    #pragma unroll
    for (int i = 0; i < 4; i++) {
        int g = t + 256 * i;
        int r = g >> 6, c4 = g & 63;
        *(float4*)&a_s[r * AST + c4 * 4] = __ldg(g4 + g);
    }
    __syncthreads();

    int tx = t & 15, ty = t >> 4;
    float4 s = __ldg((const float4*)(bd + 4 * tx));
    const float* arow = a_s + ty * AST;

    #pragma unroll 4
    for (int k = 0; k < 256; k++) {
        float a = arow[k];
        float4 wv = __ldg((const float4*)(W + k * 64 + 4 * tx));
        s.x = fmaf(a, wv.x, s.x);
        s.y = fmaf(a, wv.y, s.y);
        s.z = fmaf(a, wv.z, s.z);
        s.w = fmaf(a, wv.w, s.w);
    }
    *(float4*)(out + (row0 + ty) * 64 + 4 * tx) = s;
}

// ---------------------------------------------------------------------------
extern "C" void kernel_launch(void* const* d_in, const int* in_sizes, int n_in,
                              void* d_out, int out_size)
{
    const float* queries = (const float*)d_in[0];
    const float* values  = (const float*)d_in[1];
    const float* U_re    = (const float*)d_in[2];
    const float* U_im    = (const float*)d_in[3];
    const float* bias    = (const float*)d_in[4];
    const float* theta1  = (const float*)d_in[5];
    const float* phi1    = (const float*)d_in[6];
    const float* theta2  = (const float*)d_in[7];
    const float* phi2    = (const float*)d_in[8];
    const float* omega   = (const float*)d_in[9];
    const float* W_dense = (const float*)d_in[10];
    const float* b_dense = (const float*)d_in[11];
    float* out = (float*)d_out;

    k_compute_u<<<256, 256>>>(queries, values, U_re, U_im);
    k_recur<<<1024, 128>>>(bias, theta1, phi1, theta2, phi2, omega);
    k_proj<<<64, 256>>>(W_dense, b_dense, out);
}